// round 4
// baseline (speedup 1.0000x reference)
#include <cuda_runtime.h>
#include <math_constants.h>

// PCEN: [B=32, T=4096, F=256] fp32.
//   ema_t = w*x_t + (1-w)*ema_{t-1},  ema_{-1} = x_0
//   v     = (x*(EPS+ema)^(-g) + bias)^(1/r) - bias^(1/r)
//   out   = 2*(v - min v)/(max v - min v) - 1   (global min/max)
//
// Round 3: single-pass scan+minmax via decoupled lookback (chunk aggregates
// published with flags; carry accumulated deterministically from aggregates
// only, so FP result is replay-invariant). Rescan hits L2. Output pass uses
// sqrtf fast path when 1/root == 0.5. DRAM traffic ~402 MB (was 536).

#define EPSC 1e-6f
#define BB   32
#define TT   4096
#define FF   256
#define LL   64
#define NCHUNK (TT / LL)            // 64
#define NBLK   (BB * NCHUNK)        // 2048 blocks for KA / chains*chunks/256 for KB
#define NTHREAD (BB * NCHUNK * FF)  // 524288

__device__ float    g_S[NBLK * FF];   // chunk aggregates, [(b,c)][f]
__device__ float    g_A[NBLK * FF];   // chunk carry-ins,   [(b,c)][f]
__device__ int      g_flag[NBLK];     // aggregate-ready flags
__device__ unsigned g_minmax[2];      // ordered-uint min/max keys of u

// Monotone float <-> uint mapping (handles sign).
__device__ __forceinline__ unsigned f2key(float f) {
    unsigned u = __float_as_uint(f);
    return (u & 0x80000000u) ? ~u : (u | 0x80000000u);
}
__device__ __forceinline__ float key2f(unsigned k) {
    return __uint_as_float((k & 0x80000000u) ? (k & 0x7FFFFFFFu) : ~k);
}

// ---------------------------------------------------------------------------
// K0: reset flags + minmax (must run each graph replay).
// ---------------------------------------------------------------------------
__global__ void __launch_bounds__(256) k0_init()
{
    int tid = blockIdx.x * blockDim.x + threadIdx.x;
    if (tid < NBLK) g_flag[tid] = 0;
    if (tid == 0) {
        g_minmax[0] = 0xFFFFFFFFu;  // min key (= +inf)
        g_minmax[1] = 0x00000000u;  // max key (= -inf)
    }
}

// ---------------------------------------------------------------------------
// KA: fused chunk-scan + lookback-combine + minmax reduce.
// Block (b,c): 256 threads = 256 f lanes, chunk of L=64 timesteps.
//  1) local scan (zero carry) -> aggregate S, publish with flag
//  2) wait for predecessor flags (lower block IDs only -> deadlock-free),
//     accumulate carry A = sum_j D^(c-1-j) S_j + D^c * x[b,0,f]
//     (aggregates only: deterministic FP sequence regardless of timing)
//  3) rescan chunk (L2-hot re-read) with true carry, reduce min/max of
//     u = x * (EPS+ema)^(-g)   [v is monotone in u]
// ---------------------------------------------------------------------------
__global__ void __launch_bounds__(256) ka_scan_minmax(
    const float* __restrict__ x,
    const float* __restrict__ gain, const float* __restrict__ smooth)
{
    int bid = blockIdx.x;
    int f = threadIdx.x;
    int c = bid & (NCHUNK - 1);
    int b = bid >> 6;

    float w   = fminf(fmaxf(smooth[0], 0.0f), 1.0f);
    float omw = 1.0f - w;
    float g   = fminf(gain[0], 1.0f);
    float D = omw;                  // omw^64 via 6 squarings (exact repeated squaring)
    #pragma unroll
    for (int i = 0; i < 6; i++) D *= D;

    const float* p = x + ((size_t)(b * TT + c * LL)) * FF + f;

    // 1) local scan with zero carry
    float a = 0.0f;
    #pragma unroll 8
    for (int i = 0; i < LL; i++) {
        a = fmaf(omw, a, w * p[(size_t)i * FF]);
    }
    g_S[bid * FF + f] = a;          // aggregate
    __threadfence();                // every writer fences its own store
    __syncthreads();
    if (f == 0) atomicExch(&g_flag[bid], 1);   // release flag

    // 2) lookback: wait for all predecessors in this chain, then accumulate.
    int chainbase = (b * NCHUNK);
    if (f == 0) {
        for (int j = 0; j < c; j++) {
            while (atomicAdd(&g_flag[chainbase + j], 0) == 0) __nanosleep(40);
        }
    }
    __syncthreads();
    __threadfence();                // acquire: data loads below stay below

    float carry = 0.0f, mult = 1.0f;
    #pragma unroll 4
    for (int j = c - 1; j >= 0; j--) {
        float Sj = __ldcg(&g_S[(chainbase + j) * FF + f]);
        carry = fmaf(mult, Sj, carry);
        mult *= D;
    }
    float x0 = __ldcg(&x[(size_t)b * TT * FF + f]);   // ema_{-1} = x[b,0,f]
    float A = fmaf(mult, x0, carry);                  // mult = D^c here
    g_A[bid * FF + f] = A;

    // 3) rescan (L2-hot) + minmax of u
    a = A;
    float mn = CUDART_INF_F, mx = -CUDART_INF_F;
    #pragma unroll 4
    for (int i = 0; i < LL; i++) {
        float xv = p[(size_t)i * FF];
        a = fmaf(omw, a, w * xv);
        float u = xv * __powf(EPSC + a, -g);
        mn = fminf(mn, u);
        mx = fmaxf(mx, u);
    }

    #pragma unroll
    for (int o = 16; o; o >>= 1) {
        mn = fminf(mn, __shfl_xor_sync(0xFFFFFFFFu, mn, o));
        mx = fmaxf(mx, __shfl_xor_sync(0xFFFFFFFFu, mx, o));
    }
    __shared__ float smn[8], smx[8];
    int wid = threadIdx.x >> 5, lane = threadIdx.x & 31;
    if (lane == 0) { smn[wid] = mn; smx[wid] = mx; }
    __syncthreads();
    if (threadIdx.x == 0) {
        float bmn = smn[0], bmx = smx[0];
        #pragma unroll
        for (int i = 1; i < 8; i++) {
            bmn = fminf(bmn, smn[i]);
            bmx = fmaxf(bmx, smx[i]);
        }
        atomicMin(&g_minmax[0], f2key(bmn));
        atomicMax(&g_minmax[1], f2key(bmx));
    }
}

// ---------------------------------------------------------------------------
// KB: rescan with carry, compute v' = (u+bias)^(1/r), normalize, write.
// bias^(1/r) cancels: out = (v' - v'min)*2/(v'max - v'min) - 1.
// v'min/v'max use the SAME formula as the in-loop v' (including the sqrt
// fast path when 1/r == 0.5), so extreme elements map exactly to -1/+1.
// ---------------------------------------------------------------------------
__global__ void __launch_bounds__(256) kb_output(
    const float* __restrict__ x, float* __restrict__ out,
    const float* __restrict__ gain, const float* __restrict__ bias,
    const float* __restrict__ root, const float* __restrict__ smooth)
{
    int tid = blockIdx.x * blockDim.x + threadIdx.x;
    int f = tid & (FF - 1);
    int c = (tid >> 8) & (NCHUNK - 1);
    int b = tid >> 14;

    float w   = fminf(fmaxf(smooth[0], 0.0f), 1.0f);
    float omw = 1.0f - w;
    float g   = fminf(gain[0], 1.0f);
    float r   = fmaxf(root[0], 1.0f);
    float oor = 1.0f / r;
    float bs  = bias[0];
    bool  sq  = (oor == 0.5f);      // root == 2 -> exact sqrt fast path

    float umn = key2f(g_minmax[0]);
    float umx = key2f(g_minmax[1]);
    float vmn = sq ? sqrtf(umn + bs) : __powf(umn + bs, oor);
    float vmx = sq ? sqrtf(umx + bs) : __powf(umx + bs, oor);
    float sc  = 2.0f / (vmx - vmn);

    size_t off = ((size_t)(b * TT + c * LL)) * FF + f;
    const float* p = x + off;
    float*       q = out + off;

    float a = g_A[tid];

    #pragma unroll 8
    for (int i = 0; i < LL; i++) {
        float xv = p[(size_t)i * FF];
        a = fmaf(omw, a, w * xv);
        float u  = xv * __powf(EPSC + a, -g);
        float vp = sq ? sqrtf(u + bs) : __powf(u + bs, oor);
        q[(size_t)i * FF] = fmaf(vp - vmn, sc, -1.0f);
    }
}

extern "C" void kernel_launch(void* const* d_in, const int* in_sizes, int n_in,
                              void* d_out, int out_size)
{
    const float* x      = (const float*)d_in[0];
    const float* gain   = (const float*)d_in[1];
    const float* bias   = (const float*)d_in[2];
    const float* root   = (const float*)d_in[3];
    const float* smooth = (const float*)d_in[4];
    float* out = (float*)d_out;

    k0_init<<<NBLK / 256, 256>>>();
    ka_scan_minmax<<<NBLK, 256>>>(x, gain, smooth);
    kb_output<<<NTHREAD / 256, 256>>>(x, out, gain, bias, root, smooth);
}